// round 4
// baseline (speedup 1.0000x reference)
#include <cuda_runtime.h>
#include <math.h>

#define NN 50000
#define EE 800000
#define FF 256
#define LL 4
#define NEG_SLOPE 0.2f
#define BNEPS 1e-5f

// ---------------- scratch (static device globals: no runtime allocation) ----
__device__ float g_etmp[(size_t)EE * FF];   // e_tmp  (also e@We GEMM output)
__device__ float g_hWs[(size_t)NN * FF];
__device__ float g_hWd[(size_t)NN * FF];
__device__ float g_hWf[(size_t)NN * FF];
__device__ float g_hWb[(size_t)NN * FF];
__device__ float g_htmp[(size_t)NN * FF];   // h@Wself, later h_tmp
__device__ float g_aggf[(size_t)NN * FF];
__device__ float g_aggb[(size_t)NN * FF];
__device__ float g_logf[EE];
__device__ float g_logb[EE];
__device__ float g_mf[NN];
__device__ float g_mb[NN];
__device__ float g_denf[NN];
__device__ float g_denb[NN];
__device__ float g_statsE[2 * FF];          // sum, sumsq -> mean, invstd
__device__ float g_statsH[2 * FF];

// ---------------- small helpers -------------------------------------------
__device__ __forceinline__ void ld8(const float* p, float* v) {
    float4 a = *(const float4*)p;
    float4 b = *(const float4*)(p + 4);
    v[0] = a.x; v[1] = a.y; v[2] = a.z; v[3] = a.w;
    v[4] = b.x; v[5] = b.y; v[6] = b.z; v[7] = b.w;
}
__device__ __forceinline__ void st8(float* p, const float* v) {
    *(float4*)p       = make_float4(v[0], v[1], v[2], v[3]);
    *(float4*)(p + 4) = make_float4(v[4], v[5], v[6], v[7]);
}
__device__ __forceinline__ void atomicMaxF(float* addr, float v) {
    // sign-split trick; storage initialized to bits 0xFFFFFFFF (acts as -inf)
    if (v >= 0.f) atomicMax((int*)addr, __float_as_int(v));
    else          atomicMin((unsigned int*)addr, __float_as_uint(v));
}
__device__ __forceinline__ void redAdd4(float* p, float a, float b, float c, float d) {
    asm volatile("red.global.add.v4.f32 [%0], {%1, %2, %3, %4};"
                 :: "l"(p), "f"(a), "f"(b), "f"(c), "f"(d) : "memory");
}

__global__ void fill_f(float* p, size_t n, float v) {
    for (size_t i = (size_t)blockIdx.x * blockDim.x + threadIdx.x; i < n;
         i += (size_t)gridDim.x * blockDim.x) p[i] = v;
}
__global__ void fill_u(unsigned* p, size_t n, unsigned v) {
    for (size_t i = (size_t)blockIdx.x * blockDim.x + threadIdx.x; i < n;
         i += (size_t)gridDim.x * blockDim.x) p[i] = v;
}

// ---------------- GEMM: C[M,256] = A[M,256] @ W[256,256] -------------------
// 128x128 tile, BK=8, 8x8 per thread, 256 threads.
__global__ void __launch_bounds__(256, 2)
sgemm256(const float* __restrict__ A, const float* __restrict__ W,
         float* __restrict__ C, int M)
{
    const int BM = 128, BN = 128, BK = 8, TM = 8, TN = 8;
    __shared__ float As[BK][BM];
    __shared__ float Bs[BK][BN];

    int tid  = threadIdx.x;
    int row0 = blockIdx.y * BM;
    int col0 = blockIdx.x * BN;

    int ty = (tid / (BN / TN)) * TM;   // 0..120
    int tx = (tid % (BN / TN)) * TN;   // 0..120

    int a_row = tid / 2;               // 0..127
    int a_col = (tid % 2) * 4;         // 0 or 4
    int b_row = tid / 32;              // 0..7
    int b_col = (tid % 32) * 4;        // 0..124

    bool aval = (row0 + a_row) < M;
    const float* Ap = A + (size_t)(row0 + a_row) * FF + a_col;
    const float* Wp = W + (size_t)b_row * FF + col0 + b_col;

    float acc[TM][TN];
#pragma unroll
    for (int i = 0; i < TM; i++)
#pragma unroll
        for (int j = 0; j < TN; j++) acc[i][j] = 0.f;

    for (int k0 = 0; k0 < FF; k0 += BK) {
        float4 av = aval ? *(const float4*)(Ap + k0) : make_float4(0.f, 0.f, 0.f, 0.f);
        As[a_col + 0][a_row] = av.x;
        As[a_col + 1][a_row] = av.y;
        As[a_col + 2][a_row] = av.z;
        As[a_col + 3][a_row] = av.w;
        *(float4*)&Bs[b_row][b_col] = *(const float4*)(Wp + (size_t)k0 * FF);
        __syncthreads();
#pragma unroll
        for (int k = 0; k < BK; k++) {
            float ar[TM], br[TN];
            *(float4*)&ar[0] = *(float4*)&As[k][ty];
            *(float4*)&ar[4] = *(float4*)&As[k][ty + 4];
            *(float4*)&br[0] = *(float4*)&Bs[k][tx];
            *(float4*)&br[4] = *(float4*)&Bs[k][tx + 4];
#pragma unroll
            for (int i = 0; i < TM; i++)
#pragma unroll
                for (int j = 0; j < TN; j++) acc[i][j] += ar[i] * br[j];
        }
        __syncthreads();
    }

#pragma unroll
    for (int i = 0; i < TM; i++) {
        int r = row0 + ty + i;
        if (r < M) {
            float* cp = C + (size_t)r * FF + col0 + tx;
            *(float4*)cp       = make_float4(acc[i][0], acc[i][1], acc[i][2], acc[i][3]);
            *(float4*)(cp + 4) = make_float4(acc[i][4], acc[i][5], acc[i][6], acc[i][7]);
        }
    }
}

// ---------------- edge pass A ----------------------------------------------
// e_tmp += hWs[src] + hWd[dst]; logits; atomicMax segment maxima; BN partials.
__global__ void __launch_bounds__(256)
edgeA_kernel(float* __restrict__ etmp,
             const float* __restrict__ hWs, const float* __restrict__ hWd,
             const int* __restrict__ src, const int* __restrict__ dst,
             const float* __restrict__ af, const float* __restrict__ ab,
             float* __restrict__ logf, float* __restrict__ logb,
             float* __restrict__ mf, float* __restrict__ mb,
             float* __restrict__ stats)
{
    int lane = threadIdx.x & 31;
    int warp = (blockIdx.x * blockDim.x + threadIdx.x) >> 5;
    int nw   = (gridDim.x * blockDim.x) >> 5;
    int fb   = lane * 8;

    float a0[8], a1[8];
#pragma unroll
    for (int j = 0; j < 8; j++) { a0[j] = af[fb + j]; a1[j] = ab[fb + j]; }

    float s[8], sq[8];
#pragma unroll
    for (int j = 0; j < 8; j++) { s[j] = 0.f; sq[j] = 0.f; }

    for (int ei = warp; ei < EE; ei += nw) {
        int si = src[ei], di = dst[ei];
        float* pe = etmp + (size_t)ei * FF + fb;
        float e8[8], x8[8], y8[8], v[8];
        ld8(pe, e8);
        ld8(hWs + (size_t)si * FF + fb, x8);
        ld8(hWd + (size_t)di * FF + fb, y8);
        float df = 0.f, db = 0.f;
#pragma unroll
        for (int j = 0; j < 8; j++) {
            v[j] = e8[j] + x8[j] + y8[j];
            df += v[j] * a0[j];
            db += v[j] * a1[j];
            s[j]  += v[j];
            sq[j] += v[j] * v[j];
        }
        st8(pe, v);
#pragma unroll
        for (int o = 16; o > 0; o >>= 1) {
            df += __shfl_xor_sync(0xffffffffu, df, o);
            db += __shfl_xor_sync(0xffffffffu, db, o);
        }
        if (lane == 0) {
            float lf = df > 0.f ? df : NEG_SLOPE * df;
            float lb = db > 0.f ? db : NEG_SLOPE * db;
            logf[ei] = lf;
            logb[ei] = lb;
            atomicMaxF(&mf[di], lf);
            atomicMaxF(&mb[si], lb);
        }
    }
#pragma unroll
    for (int j = 0; j < 8; j++) {
        atomicAdd(&stats[fb + j], s[j]);
        atomicAdd(&stats[FF + fb + j], sq[j]);
    }
}

// ---------------- BN finalize (stats -> mean, invstd) ----------------------
__global__ void bnfin_kernel(float* stats, float inv_cnt) {
    int f = threadIdx.x;
    float mu  = stats[f] * inv_cnt;
    float var = stats[FF + f] * inv_cnt - mu * mu;
    stats[f]      = mu;
    stats[FF + f] = rsqrtf(var + BNEPS);
}

// ---------------- edge pass B ----------------------------------------------
// e_out = e_in + relu(bn(e_tmp)); ex = exp(log - m[seg]); den atomic;
// agg_{f,b} scatter of ex * hW{f,b}[gather] via red.v4.
__global__ void __launch_bounds__(256)
edgeB_kernel(const float* __restrict__ etmp,
             const float* e_in, float* e_out,
             const float* __restrict__ logf, const float* __restrict__ logb,
             const float* __restrict__ mf, const float* __restrict__ mb,
             const int* __restrict__ src, const int* __restrict__ dst,
             const float* __restrict__ hWf, const float* __restrict__ hWb,
             float* __restrict__ denf, float* __restrict__ denb,
             float* __restrict__ aggf, float* __restrict__ aggb,
             const float* __restrict__ stats,
             const float* __restrict__ ge, const float* __restrict__ be)
{
    int lane = threadIdx.x & 31;
    int warp = (blockIdx.x * blockDim.x + threadIdx.x) >> 5;
    int nw   = (gridDim.x * blockDim.x) >> 5;
    int fb   = lane * 8;

    float mu[8], is[8], gg[8], bb[8];
#pragma unroll
    for (int j = 0; j < 8; j++) {
        mu[j] = stats[fb + j];
        is[j] = stats[FF + fb + j];
        gg[j] = ge[fb + j];
        bb[j] = be[fb + j];
    }

    for (int ei = warp; ei < EE; ei += nw) {
        int si = src[ei], di = dst[ei];
        float exf = 0.f, exb = 0.f;
        if (lane == 0) {
            exf = expf(logf[ei] - mf[di]);
            exb = expf(logb[ei] - mb[si]);
            atomicAdd(&denf[di], exf);
            atomicAdd(&denb[si], exb);
        }
        exf = __shfl_sync(0xffffffffu, exf, 0);
        exb = __shfl_sync(0xffffffffu, exb, 0);

        // edge feature residual update
        float t[8], ein[8], o[8];
        ld8(etmp + (size_t)ei * FF + fb, t);
        ld8(e_in + (size_t)ei * FF + fb, ein);
#pragma unroll
        for (int j = 0; j < 8; j++) {
            float bn = (t[j] - mu[j]) * is[j] * gg[j] + bb[j];
            o[j] = ein[j] + (bn > 0.f ? bn : 0.f);
        }
        st8(e_out + (size_t)ei * FF + fb, o);

        // attention-weighted scatter
        float wf[8], wb[8];
        ld8(hWf + (size_t)si * FF + fb, wf);
        ld8(hWb + (size_t)di * FF + fb, wb);
        float* pf = aggf + (size_t)di * FF + fb;
        float* pb = aggb + (size_t)si * FF + fb;
        redAdd4(pf,     exf * wf[0], exf * wf[1], exf * wf[2], exf * wf[3]);
        redAdd4(pf + 4, exf * wf[4], exf * wf[5], exf * wf[6], exf * wf[7]);
        redAdd4(pb,     exb * wb[0], exb * wb[1], exb * wb[2], exb * wb[3]);
        redAdd4(pb + 4, exb * wb[4], exb * wb[5], exb * wb[6], exb * wb[7]);
    }
}

// ---------------- node pass A ----------------------------------------------
// h_tmp = hWself + aggf/(denf+1e-9) + aggb/(denb+1e-9); BN partials over N.
__global__ void __launch_bounds__(256)
nodeA_kernel(float* __restrict__ htmp,
             const float* __restrict__ aggf, const float* __restrict__ aggb,
             const float* __restrict__ denf, const float* __restrict__ denb,
             float* __restrict__ stats)
{
    int lane = threadIdx.x & 31;
    int warp = (blockIdx.x * blockDim.x + threadIdx.x) >> 5;
    int nw   = (gridDim.x * blockDim.x) >> 5;
    int fb   = lane * 8;

    float s[8], sq[8];
#pragma unroll
    for (int j = 0; j < 8; j++) { s[j] = 0.f; sq[j] = 0.f; }

    for (int n = warp; n < NN; n += nw) {
        float rf = 1.f / (denf[n] + 1e-9f);
        float rb = 1.f / (denb[n] + 1e-9f);
        float hv[8], afv[8], abv[8], v[8];
        float* ph = htmp + (size_t)n * FF + fb;
        ld8(ph, hv);
        ld8(aggf + (size_t)n * FF + fb, afv);
        ld8(aggb + (size_t)n * FF + fb, abv);
#pragma unroll
        for (int j = 0; j < 8; j++) {
            v[j] = hv[j] + afv[j] * rf + abv[j] * rb;
            s[j]  += v[j];
            sq[j] += v[j] * v[j];
        }
        st8(ph, v);
    }
#pragma unroll
    for (int j = 0; j < 8; j++) {
        atomicAdd(&stats[fb + j], s[j]);
        atomicAdd(&stats[FF + fb + j], sq[j]);
    }
}

// ---------------- node pass B ----------------------------------------------
// h_out = h_in + relu(bn(h_tmp))
__global__ void __launch_bounds__(256)
nodeB_kernel(const float* __restrict__ htmp, const float* h_in, float* h_out,
             const float* __restrict__ stats,
             const float* __restrict__ gh, const float* __restrict__ bh)
{
    int i = blockIdx.x * blockDim.x + threadIdx.x;   // float4 index
    const int NV = NN * FF / 4;
    if (i >= NV) return;
    int c = (i & (FF / 4 - 1)) * 4;
    float4 t  = ((const float4*)htmp)[i];
    float4 hv = ((const float4*)h_in)[i];
    float r[4] = {t.x, t.y, t.z, t.w};
    float h[4] = {hv.x, hv.y, hv.z, hv.w};
    float o[4];
#pragma unroll
    for (int j = 0; j < 4; j++) {
        float bn = (r[j] - stats[c + j]) * stats[FF + c + j] * gh[c + j] + bh[c + j];
        o[j] = h[j] + (bn > 0.f ? bn : 0.f);
    }
    ((float4*)h_out)[i] = make_float4(o[0], o[1], o[2], o[3]);
}

// ---------------- launch ---------------------------------------------------
extern "C" void kernel_launch(void* const* d_in, const int* in_sizes, int n_in,
                              void* d_out, int out_size)
{
    (void)in_sizes; (void)n_in; (void)out_size;
    const float* h0    = (const float*)d_in[0];
    const float* e0    = (const float*)d_in[1];
    const int*   src   = (const int*)d_in[2];
    const int*   dst   = (const int*)d_in[3];
    const float* We    = (const float*)d_in[4];
    const float* Ws    = (const float*)d_in[5];
    const float* Wd    = (const float*)d_in[6];
    const float* Wself = (const float*)d_in[7];
    const float* Wf    = (const float*)d_in[8];
    const float* Wb    = (const float*)d_in[9];
    const float* att_f = (const float*)d_in[10];
    const float* att_b = (const float*)d_in[11];
    const float* g_e   = (const float*)d_in[12];
    const float* b_e   = (const float*)d_in[13];
    const float* g_h   = (const float*)d_in[14];
    const float* b_h   = (const float*)d_in[15];

    float* outh = (float*)d_out;
    float* oute = outh + (size_t)NN * FF;

    float *etmp, *hWs, *hWd, *hWf, *hWb, *htmp, *aggf, *aggb;
    float *logf, *logb, *mf, *mb, *denf, *denb, *stE, *stH;
    cudaGetSymbolAddress((void**)&etmp, g_etmp);
    cudaGetSymbolAddress((void**)&hWs,  g_hWs);
    cudaGetSymbolAddress((void**)&hWd,  g_hWd);
    cudaGetSymbolAddress((void**)&hWf,  g_hWf);
    cudaGetSymbolAddress((void**)&hWb,  g_hWb);
    cudaGetSymbolAddress((void**)&htmp, g_htmp);
    cudaGetSymbolAddress((void**)&aggf, g_aggf);
    cudaGetSymbolAddress((void**)&aggb, g_aggb);
    cudaGetSymbolAddress((void**)&logf, g_logf);
    cudaGetSymbolAddress((void**)&logb, g_logb);
    cudaGetSymbolAddress((void**)&mf,   g_mf);
    cudaGetSymbolAddress((void**)&mb,   g_mb);
    cudaGetSymbolAddress((void**)&denf, g_denf);
    cudaGetSymbolAddress((void**)&denb, g_denb);
    cudaGetSymbolAddress((void**)&stE,  g_statsE);
    cudaGetSymbolAddress((void**)&stH,  g_statsH);

    const size_t FFm = (size_t)FF * FF;
    dim3 gNode(2, (NN + 127) / 128);
    dim3 gEdge(2, (EE + 127) / 128);

    for (int l = 0; l < LL; l++) {
        const float* hcur = l ? outh : h0;
        const float* ecur = l ? oute : e0;

        // node projections (from current h) + edge GEMM
        sgemm256<<<gNode, 256>>>(hcur, Ws    + l * FFm, hWs,  NN);
        sgemm256<<<gNode, 256>>>(hcur, Wd    + l * FFm, hWd,  NN);
        sgemm256<<<gNode, 256>>>(hcur, Wf    + l * FFm, hWf,  NN);
        sgemm256<<<gNode, 256>>>(hcur, Wb    + l * FFm, hWb,  NN);
        sgemm256<<<gNode, 256>>>(hcur, Wself + l * FFm, htmp, NN);
        sgemm256<<<gEdge, 256>>>(ecur, We    + l * FFm, etmp, EE);

        // per-layer scratch init
        fill_f<<<4096, 256>>>(aggf, (size_t)NN * FF, 0.f);
        fill_f<<<4096, 256>>>(aggb, (size_t)NN * FF, 0.f);
        fill_f<<<64, 256>>>(denf, NN, 0.f);
        fill_f<<<64, 256>>>(denb, NN, 0.f);
        fill_u<<<64, 256>>>((unsigned*)mf, NN, 0xFFFFFFFFu);
        fill_u<<<64, 256>>>((unsigned*)mb, NN, 0xFFFFFFFFu);
        fill_f<<<1, 512>>>(stE, 2 * FF, 0.f);
        fill_f<<<1, 512>>>(stH, 2 * FF, 0.f);

        edgeA_kernel<<<1024, 256>>>(etmp, hWs, hWd, src, dst,
                                    att_f + (size_t)l * FF, att_b + (size_t)l * FF,
                                    logf, logb, mf, mb, stE);
        bnfin_kernel<<<1, FF>>>(stE, 1.f / EE);
        edgeB_kernel<<<2048, 256>>>(etmp, ecur, oute, logf, logb, mf, mb,
                                    src, dst, hWf, hWb, denf, denb, aggf, aggb,
                                    stE, g_e + (size_t)l * FF, b_e + (size_t)l * FF);
        nodeA_kernel<<<512, 256>>>(htmp, aggf, aggb, denf, denb, stH);
        bnfin_kernel<<<1, FF>>>(stH, 1.f / NN);
        nodeB_kernel<<<(NN * FF / 4 + 255) / 256, 256>>>(
            htmp, hcur, outh, stH, g_h + (size_t)l * FF, b_h + (size_t)l * FF);
    }
}

// round 6
// speedup vs baseline: 1.4133x; 1.4133x over previous
#include <cuda_runtime.h>
#include <cuda_bf16.h>
#include <math.h>
#include <stdint.h>

#define NN 50000
#define EE 800000
#define FF 256
#define LL 4
#define NEG_SLOPE 0.2f
#define BNEPS 1e-5f

// ---------------- scratch (static device globals: no runtime allocation) ----
__device__ float g_etmp[(size_t)EE * FF];   // e_tmp (edge GEMM output)
__device__ float g_hWs[(size_t)NN * FF];
__device__ float g_hWd[(size_t)NN * FF];
__device__ float g_hWf[(size_t)NN * FF];
__device__ float g_hWb[(size_t)NN * FF];
__device__ float g_htmp[(size_t)NN * FF];
__device__ float g_aggf[(size_t)NN * FF];
__device__ float g_aggb[(size_t)NN * FF];
__device__ float g_logf[EE];
__device__ float g_logb[EE];
__device__ float g_mf[NN];
__device__ float g_mb[NN];
__device__ float g_denf[NN];
__device__ float g_denb[NN];
__device__ float g_statsE[2 * FF];
__device__ float g_statsH[2 * FF];
// bf16 hi/lo split inputs for tensor-core GEMMs
__device__ __nv_bfloat16 g_ehi[(size_t)EE * FF];
__device__ __nv_bfloat16 g_elo[(size_t)EE * FF];
__device__ __nv_bfloat16 g_hhi[(size_t)NN * FF];
__device__ __nv_bfloat16 g_hlo[(size_t)NN * FF];
// transposed bf16 hi/lo weights: [6 types][LL][256n][256k]
__device__ __nv_bfloat16 g_wthi[(size_t)6 * LL * FF * FF];
__device__ __nv_bfloat16 g_wtlo[(size_t)6 * LL * FF * FF];

// ---------------- small helpers -------------------------------------------
__device__ __forceinline__ void ld8(const float* p, float* v) {
    float4 a = *(const float4*)p;
    float4 b = *(const float4*)(p + 4);
    v[0] = a.x; v[1] = a.y; v[2] = a.z; v[3] = a.w;
    v[4] = b.x; v[5] = b.y; v[6] = b.z; v[7] = b.w;
}
__device__ __forceinline__ void st8(float* p, const float* v) {
    *(float4*)p       = make_float4(v[0], v[1], v[2], v[3]);
    *(float4*)(p + 4) = make_float4(v[4], v[5], v[6], v[7]);
}
__device__ __forceinline__ void atomicMaxF(float* addr, float v) {
    if (v >= 0.f) atomicMax((int*)addr, __float_as_int(v));
    else          atomicMin((unsigned int*)addr, __float_as_uint(v));
}
__device__ __forceinline__ void redAdd4(float* p, float a, float b, float c, float d) {
    asm volatile("red.global.add.v4.f32 [%0], {%1, %2, %3, %4};"
                 :: "l"(p), "f"(a), "f"(b), "f"(c), "f"(d) : "memory");
}
// split 8 fp32 -> packed bf16 hi / lo uint4s
__device__ __forceinline__ void split_pack(const float* v, uint4* ph, uint4* pl) {
    unsigned hw[4], lw[4];
#pragma unroll
    for (int j = 0; j < 4; j++) {
        __nv_bfloat16 h0 = __float2bfloat16(v[2 * j]);
        __nv_bfloat16 h1 = __float2bfloat16(v[2 * j + 1]);
        __nv_bfloat16 l0 = __float2bfloat16(v[2 * j]     - __bfloat162float(h0));
        __nv_bfloat16 l1 = __float2bfloat16(v[2 * j + 1] - __bfloat162float(h1));
        hw[j] = (unsigned)__bfloat16_as_ushort(h0) | ((unsigned)__bfloat16_as_ushort(h1) << 16);
        lw[j] = (unsigned)__bfloat16_as_ushort(l0) | ((unsigned)__bfloat16_as_ushort(l1) << 16);
    }
    *ph = make_uint4(hw[0], hw[1], hw[2], hw[3]);
    *pl = make_uint4(lw[0], lw[1], lw[2], lw[3]);
}

__global__ void fill_f(float* p, size_t n, float v) {
    for (size_t i = (size_t)blockIdx.x * blockDim.x + threadIdx.x; i < n;
         i += (size_t)gridDim.x * blockDim.x) p[i] = v;
}
__global__ void fill_u(unsigned* p, size_t n, unsigned v) {
    for (size_t i = (size_t)blockIdx.x * blockDim.x + threadIdx.x; i < n;
         i += (size_t)gridDim.x * blockDim.x) p[i] = v;
}

// ---------------- mma.sync primitives (plain sm_80 ISA, no 'a' features) ---
__device__ __forceinline__ uint32_t s2u(const void* p) {
    uint32_t a;
    asm("{ .reg .u64 t; cvta.to.shared.u64 t, %1; cvt.u32.u64 %0, t; }"
        : "=r"(a) : "l"(p));
    return a;
}
__device__ __forceinline__ void cpa16(uint32_t s, const void* g) {
    asm volatile("cp.async.cg.shared.global [%0], [%1], 16;"
                 :: "r"(s), "l"(g) : "memory");
}
__device__ __forceinline__ void cp_commit() {
    asm volatile("cp.async.commit_group;" ::: "memory");
}
template <int N>
__device__ __forceinline__ void cp_wait() {
    asm volatile("cp.async.wait_group %0;" :: "n"(N) : "memory");
}
__device__ __forceinline__ void ldm4(uint32_t* r, uint32_t a) {
    asm volatile("ldmatrix.sync.aligned.m8n8.x4.shared.b16 {%0,%1,%2,%3}, [%4];"
                 : "=r"(r[0]), "=r"(r[1]), "=r"(r[2]), "=r"(r[3]) : "r"(a));
}
__device__ __forceinline__ void mma16816(float* d, const uint32_t* a, const uint32_t* b) {
    asm volatile(
        "mma.sync.aligned.m16n8k16.row.col.f32.bf16.bf16.f32 "
        "{%0,%1,%2,%3}, {%4,%5,%6,%7}, {%8,%9}, {%0,%1,%2,%3};"
        : "+f"(d[0]), "+f"(d[1]), "+f"(d[2]), "+f"(d[3])
        : "r"(a[0]), "r"(a[1]), "r"(a[2]), "r"(a[3]), "r"(b[0]), "r"(b[1]));
}

// ---------------- tensor-core GEMM: C[M,256] = A[M,256] @ W[256,256] -------
// A bf16 hi/lo [M,256] row-major; W TRANSPOSED bf16 hi/lo [256n][256k].
// CTA tile 128x128, 8 warps (2m x 4n), warp tile 64x32, BK=32, 2-stage cp.async.
// SMEM tile layout: 128 rows x 32 bf16, padded row stride 80B (conflict-free
// ldmatrix: 80 mod 128 cycles all 8 phase offsets).
#define BK 32
#define ROWB 80                              // bytes per smem row
#define TILEB (128 * ROWB)                   // 10240 per tile
#define STAGEB (4 * TILEB)                   // Ah, Al, Bh, Bl
#define GEMM_SMEM (2 * STAGEB)               // 81920

__global__ void __launch_bounds__(256, 1)
gemm_mma(const __nv_bfloat16* __restrict__ Ahi, const __nv_bfloat16* __restrict__ Alo,
         const __nv_bfloat16* __restrict__ Bhi, const __nv_bfloat16* __restrict__ Blo,
         float* __restrict__ C, int M)
{
    extern __shared__ __align__(128) char sm[];
    uint32_t sb = s2u(sm);
    int tid = threadIdx.x;
    int wid = tid >> 5, lane = tid & 31;
    int row0 = blockIdx.y * 128;
    int col0 = blockIdx.x * 128;
    int wm = (wid >> 2) * 64;       // warp m offset in tile
    int wn = (wid & 3) * 32;        // warp n offset in tile

    float acc[4][4][4];
#pragma unroll
    for (int i = 0; i < 4; i++)
#pragma unroll
        for (int j = 0; j < 4; j++)
#pragma unroll
            for (int q = 0; q < 4; q++) acc[i][j][q] = 0.f;

    // per-thread prefetch addresses: 2 chunks of 16B per tile per thread
    int c0 = tid, c1 = tid + 256;            // chunk ids 0..511
    int r0c = c0 >> 2, cc0 = c0 & 3;
    int r1c = c1 >> 2, cc1 = c1 & 3;
    int ga0 = min(row0 + r0c, M - 1);
    int ga1 = min(row0 + r1c, M - 1);
    int gb0 = col0 + r0c;
    int gb1 = col0 + r1c;
    uint32_t so0 = (uint32_t)(r0c * ROWB + cc0 * 16);
    uint32_t so1 = (uint32_t)(r1c * ROWB + cc1 * 16);

#define PREFETCH(ks, buf) do {                                                   \
        int k0 = (ks) * BK;                                                      \
        uint32_t s0 = sb + (buf) * STAGEB + so0;                                 \
        uint32_t s1 = sb + (buf) * STAGEB + so1;                                 \
        cpa16(s0,              Ahi + (size_t)ga0 * FF + k0 + cc0 * 8);           \
        cpa16(s0 + TILEB,      Alo + (size_t)ga0 * FF + k0 + cc0 * 8);           \
        cpa16(s0 + 2 * TILEB,  Bhi + (size_t)gb0 * FF + k0 + cc0 * 8);           \
        cpa16(s0 + 3 * TILEB,  Blo + (size_t)gb0 * FF + k0 + cc0 * 8);           \
        cpa16(s1,              Ahi + (size_t)ga1 * FF + k0 + cc1 * 8);           \
        cpa16(s1 + TILEB,      Alo + (size_t)ga1 * FF + k0 + cc1 * 8);           \
        cpa16(s1 + 2 * TILEB,  Bhi + (size_t)gb1 * FF + k0 + cc1 * 8);           \
        cpa16(s1 + 3 * TILEB,  Blo + (size_t)gb1 * FF + k0 + cc1 * 8);           \
        cp_commit();                                                             \
    } while (0)

    // ldmatrix lane addressing (constant per thread)
    int a_row  = wm + (lane & 15);           // + i*16
    int a_cch  = (lane >> 4) & 1;            // k sub-chunk 0/8
    int b_row  = wn + (lane & 7) + ((lane >> 4) & 1) * 8;   // + jj*16
    int b_cch  = ((lane >> 3) & 1) * 8;

    PREFETCH(0, 0);

    for (int ks = 0; ks < FF / BK; ks++) {
        int buf = ks & 1;
        if (ks < FF / BK - 1) { PREFETCH(ks + 1, buf ^ 1); cp_wait<1>(); }
        else                  { cp_wait<0>(); }
        __syncthreads();

        uint32_t base = sb + buf * STAGEB;
#pragma unroll
        for (int kc = 0; kc < 2; kc++) {
            int klocal = kc * 16;
            uint32_t ah[4][4], al[4][4];
#pragma unroll
            for (int i = 0; i < 4; i++) {
                uint32_t ad = base + (uint32_t)((a_row + i * 16) * ROWB
                                                + (klocal + a_cch * 8) * 2);
                ldm4(ah[i], ad);
                ldm4(al[i], ad + TILEB);
            }
            uint32_t bh[2][4], bl[2][4];
#pragma unroll
            for (int jj = 0; jj < 2; jj++) {
                uint32_t bd = base + 2 * TILEB
                            + (uint32_t)((b_row + jj * 16) * ROWB
                                         + (klocal + b_cch) * 2);
                ldm4(bh[jj], bd);
                ldm4(bl[jj], bd + TILEB);
            }
#pragma unroll
            for (int i = 0; i < 4; i++)
#pragma unroll
                for (int j = 0; j < 4; j++) {
                    const uint32_t* ph = &bh[j >> 1][(j & 1) * 2];
                    const uint32_t* pl = &bl[j >> 1][(j & 1) * 2];
                    mma16816(acc[i][j], ah[i], ph);
                    mma16816(acc[i][j], ah[i], pl);
                    mma16816(acc[i][j], al[i], ph);
                }
        }
        __syncthreads();
    }

    // epilogue
#pragma unroll
    for (int i = 0; i < 4; i++) {
        int r = row0 + wm + i * 16 + (lane >> 2);
        int cbase = col0 + wn + (lane & 3) * 2;
        if (r < M) {
            float* cp = C + (size_t)r * FF + cbase;
#pragma unroll
            for (int j = 0; j < 4; j++)
                *(float2*)(cp + j * 8) = make_float2(acc[i][j][0], acc[i][j][1]);
        }
        if (r + 8 < M) {
            float* cp = C + (size_t)(r + 8) * FF + cbase;
#pragma unroll
            for (int j = 0; j < 4; j++)
                *(float2*)(cp + j * 8) = make_float2(acc[i][j][2], acc[i][j][3]);
        }
    }
}

// ---------------- weight transpose + bf16 split ----------------------------
// in: W [LL][256k][256n] fp32;  out: [LL][256n][256k] bf16 hi/lo
__global__ void prep_w(const float* __restrict__ W,
                       __nv_bfloat16* __restrict__ hi, __nv_bfloat16* __restrict__ lo)
{
    int l   = blockIdx.x >> 8;
    int blk = blockIdx.x & 255;
    int i   = blk * 256 + threadIdx.x;     // 0..65535
    int n = i >> 8, k = i & 255;
    size_t off = (size_t)l * FF * FF;
    float w = W[off + (size_t)k * FF + n];
    __nv_bfloat16 h = __float2bfloat16(w);
    hi[off + i] = h;
    lo[off + i] = __float2bfloat16(w - __bfloat162float(h));
}

// ---------------- fp32 -> bf16 hi/lo split (bulk) --------------------------
__global__ void split8(const float* __restrict__ x,
                       __nv_bfloat16* __restrict__ hi, __nv_bfloat16* __restrict__ lo,
                       size_t n8)
{
    for (size_t i = (size_t)blockIdx.x * blockDim.x + threadIdx.x; i < n8;
         i += (size_t)gridDim.x * blockDim.x) {
        float v[8];
        ld8(x + i * 8, v);
        uint4 uh, ul;
        split_pack(v, &uh, &ul);
        *(uint4*)(hi + i * 8) = uh;
        *(uint4*)(lo + i * 8) = ul;
    }
}

// ---------------- edge pass A ----------------------------------------------
__global__ void __launch_bounds__(256)
edgeA_kernel(float* __restrict__ etmp,
             const float* __restrict__ hWs, const float* __restrict__ hWd,
             const int* __restrict__ src, const int* __restrict__ dst,
             const float* __restrict__ af, const float* __restrict__ ab,
             float* __restrict__ logf, float* __restrict__ logb,
             float* __restrict__ mf, float* __restrict__ mb,
             float* __restrict__ stats)
{
    int lane = threadIdx.x & 31;
    int warp = (blockIdx.x * blockDim.x + threadIdx.x) >> 5;
    int nw   = (gridDim.x * blockDim.x) >> 5;
    int fb   = lane * 8;

    float a0[8], a1[8];
#pragma unroll
    for (int j = 0; j < 8; j++) { a0[j] = af[fb + j]; a1[j] = ab[fb + j]; }

    float s[8], sq[8];
#pragma unroll
    for (int j = 0; j < 8; j++) { s[j] = 0.f; sq[j] = 0.f; }

    for (int ei = warp; ei < EE; ei += nw) {
        int si = src[ei], di = dst[ei];
        float* pe = etmp + (size_t)ei * FF + fb;
        float e8[8], x8[8], y8[8], v[8];
        ld8(pe, e8);
        ld8(hWs + (size_t)si * FF + fb, x8);
        ld8(hWd + (size_t)di * FF + fb, y8);
        float df = 0.f, db = 0.f;
#pragma unroll
        for (int j = 0; j < 8; j++) {
            v[j] = e8[j] + x8[j] + y8[j];
            df += v[j] * a0[j];
            db += v[j] * a1[j];
            s[j]  += v[j];
            sq[j] += v[j] * v[j];
        }
        st8(pe, v);
#pragma unroll
        for (int o = 16; o > 0; o >>= 1) {
            df += __shfl_xor_sync(0xffffffffu, df, o);
            db += __shfl_xor_sync(0xffffffffu, db, o);
        }
        if (lane == 0) {
            float lf = df > 0.f ? df : NEG_SLOPE * df;
            float lb = db > 0.f ? db : NEG_SLOPE * db;
            logf[ei] = lf;
            logb[ei] = lb;
            atomicMaxF(&mf[di], lf);
            atomicMaxF(&mb[si], lb);
        }
    }
#pragma unroll
    for (int j = 0; j < 8; j++) {
        atomicAdd(&stats[fb + j], s[j]);
        atomicAdd(&stats[FF + fb + j], sq[j]);
    }
}

// ---------------- BN finalize ----------------------------------------------
__global__ void bnfin_kernel(float* stats, float inv_cnt) {
    int f = threadIdx.x;
    float mu  = stats[f] * inv_cnt;
    float var = stats[FF + f] * inv_cnt - mu * mu;
    stats[f]      = mu;
    stats[FF + f] = rsqrtf(var + BNEPS);
}

// ---------------- edge pass B ----------------------------------------------
__global__ void __launch_bounds__(256)
edgeB_kernel(const float* __restrict__ etmp,
             const float* e_in, float* e_out,
             const float* __restrict__ logf, const float* __restrict__ logb,
             const float* __restrict__ mf, const float* __restrict__ mb,
             const int* __restrict__ src, const int* __restrict__ dst,
             const float* __restrict__ hWf, const float* __restrict__ hWb,
             float* __restrict__ denf, float* __restrict__ denb,
             float* __restrict__ aggf, float* __restrict__ aggb,
             const float* __restrict__ stats,
             const float* __restrict__ ge, const float* __restrict__ be,
             __nv_bfloat16* __restrict__ ehi, __nv_bfloat16* __restrict__ elo,
             int wsplit)
{
    int lane = threadIdx.x & 31;
    int warp = (blockIdx.x * blockDim.x + threadIdx.x) >> 5;
    int nw   = (gridDim.x * blockDim.x) >> 5;
    int fb   = lane * 8;

    float mu[8], is[8], gg[8], bb[8];
#pragma unroll
    for (int j = 0; j < 8; j++) {
        mu[j] = stats[fb + j];
        is[j] = stats[FF + fb + j];
        gg[j] = ge[fb + j];
        bb[j] = be[fb + j];
    }

    for (int ei = warp; ei < EE; ei += nw) {
        int si = src[ei], di = dst[ei];
        float exf = 0.f, exb = 0.f;
        if (lane == 0) {
            exf = expf(logf[ei] - mf[di]);
            exb = expf(logb[ei] - mb[si]);
            atomicAdd(&denf[di], exf);
            atomicAdd(&denb[si], exb);
        }
        exf = __shfl_sync(0xffffffffu, exf, 0);
        exb = __shfl_sync(0xffffffffu, exb, 0);

        float t[8], ein[8], o[8];
        ld8(etmp + (size_t)ei * FF + fb, t);
        ld8(e_in + (size_t)ei * FF + fb, ein);
#pragma unroll
        for (int j = 0; j < 8; j++) {
            float bn = (t[j] - mu[j]) * is[j] * gg[j] + bb[j];
            o[j] = ein[j] + (bn > 0.f ? bn : 0.f);
        }
        st8(e_out + (size_t)ei * FF + fb, o);
        if (wsplit) {
            uint4 uh, ul;
            split_pack(o, &uh, &ul);
            *(uint4*)(ehi + (size_t)ei * FF + fb) = uh;
            *(uint4*)(elo + (size_t)ei * FF + fb) = ul;
        }

        float wf[8], wb[8];
        ld8(hWf + (size_t)si * FF + fb, wf);
        ld8(hWb + (size_t)di * FF + fb, wb);
        float* pf = aggf + (size_t)di * FF + fb;
        float* pb = aggb + (size_t)si * FF + fb;
        redAdd4(pf,     exf * wf[0], exf * wf[1], exf * wf[2], exf * wf[3]);
        redAdd4(pf + 4, exf * wf[4], exf * wf[5], exf * wf[6], exf * wf[7]);
        redAdd4(pb,     exb * wb[0], exb * wb[1], exb * wb[2], exb * wb[3]);
        redAdd4(pb + 4, exb * wb[4], exb * wb[5], exb * wb[6], exb * wb[7]);
    }
}

// ---------------- node pass A ----------------------------------------------
__global__ void __launch_bounds__(256)
nodeA_kernel(float* __restrict__ htmp,
             const float* __restrict__ aggf, const float* __restrict__ aggb,
             const float* __restrict__ denf, const float* __restrict__ denb,
             float* __restrict__ stats)
{
    int lane = threadIdx.x & 31;
    int warp = (blockIdx.x * blockDim.x + threadIdx.x) >> 5;
    int nw   = (gridDim.x * blockDim.x) >> 5;
    int fb   = lane * 8;

    float s[8], sq[8];
#pragma unroll
    for (int j = 0; j < 8; j++) { s[j] = 0.f; sq[j] = 0.f; }

    for (int n = warp; n < NN; n += nw) {
        float rf = 1.f / (denf[n] + 1e-9f);
        float rb = 1.f / (denb[n] + 1e-9f);
        float hv[8], afv[8], abv[8], v[8];
        float* ph = htmp + (size_t)n * FF + fb;
        ld8(ph, hv);
        ld8(aggf + (size_t)n * FF + fb, afv);
        ld8(aggb + (size_t)n * FF + fb, abv);
#pragma unroll
        for (int j = 0; j < 8; j++) {
            v[j] = hv[j] + afv[j] * rf + abv[j] * rb;
            s[j]  += v[j];
            sq[j] += v[j] * v[j];
        }
        st8(ph, v);
    }
#pragma unroll
    for (int j = 0; j < 8; j++) {
        atomicAdd(&stats[fb + j], s[j]);
        atomicAdd(&stats[FF + fb + j], sq[j]);
    }
}

// ---------------- node pass B ----------------------------------------------
__global__ void __launch_bounds__(256)
nodeB_kernel(const float* __restrict__ htmp, const float* h_in, float* h_out,
             const float* __restrict__ stats,
             const float* __restrict__ gh, const float* __restrict__ bh,
             __nv_bfloat16* __restrict__ hhi, __nv_bfloat16* __restrict__ hlo,
             int wsplit)
{
    int i = blockIdx.x * blockDim.x + threadIdx.x;   // 8-element group index
    const int NV = NN * FF / 8;
    if (i >= NV) return;
    int c = (i & (FF / 8 - 1)) * 8;
    float t[8], hv[8], o[8];
    ld8(htmp + (size_t)i * 8, t);
    ld8(h_in + (size_t)i * 8, hv);
#pragma unroll
    for (int j = 0; j < 8; j++) {
        float bn = (t[j] - stats[c + j]) * stats[FF + c + j] * gh[c + j] + bh[c + j];
        o[j] = hv[j] + (bn > 0.f ? bn : 0.f);
    }
    st8(h_out + (size_t)i * 8, o);
    if (wsplit) {
        uint4 uh, ul;
        split_pack(o, &uh, &ul);
        *(uint4*)(hhi + (size_t)i * 8) = uh;
        *(uint4*)(hlo + (size_t)i * 8) = ul;
    }
}

// ---------------- launch ---------------------------------------------------
extern "C" void kernel_launch(void* const* d_in, const int* in_sizes, int n_in,
                              void* d_out, int out_size)
{
    (void)in_sizes; (void)n_in; (void)out_size;
    const float* h0    = (const float*)d_in[0];
    const float* e0    = (const float*)d_in[1];
    const int*   src   = (const int*)d_in[2];
    const int*   dst   = (const int*)d_in[3];
    const float* Wsrc[6] = {
        (const float*)d_in[4],   // We
        (const float*)d_in[5],   // Ws
        (const float*)d_in[6],   // Wd
        (const float*)d_in[7],   // Wself
        (const float*)d_in[8],   // Wf
        (const float*)d_in[9],   // Wb
    };
    const float* att_f = (const float*)d_in[10];
    const float* att_b = (const float*)d_in[11];
    const float* g_e   = (const float*)d_in[12];
    const float* b_e   = (const float*)d_in[13];
    const float* g_h   = (const float*)d_in[14];
    const float* b_h   = (const float*)d_in[15];

    float* outh = (float*)d_out;
    float* oute = outh + (size_t)NN * FF;

    float *etmp, *hWs, *hWd, *hWf, *hWb, *htmp, *aggf, *aggb;
    float *logf, *logb, *mf, *mb, *denf, *denb, *stE, *stH;
    __nv_bfloat16 *ehi, *elo, *hhi, *hlo, *wthi, *wtlo;
    cudaGetSymbolAddress((void**)&etmp, g_etmp);
    cudaGetSymbolAddress((void**)&hWs,  g_hWs);
    cudaGetSymbolAddress((void**)&hWd,  g_hWd);
    cudaGetSymbolAddress((void**)&hWf,  g_hWf);
    cudaGetSymbolAddress((void**)&hWb,  g_hWb);
    cudaGetSymbolAddress((void**)&htmp, g_htmp);
    cudaGetSymbolAddress((void**)&aggf, g_aggf);
    cudaGetSymbolAddress((void**)&aggb, g_aggb);
    cudaGetSymbolAddress((void**)&logf, g_logf);
    cudaGetSymbolAddress((void**)&logb, g_logb);
    cudaGetSymbolAddress((void**)&mf,   g_mf);
    cudaGetSymbolAddress((void**)&mb,   g_mb);
    cudaGetSymbolAddress((void**)&denf, g_denf);
    cudaGetSymbolAddress((void**)&denb, g_denb);
    cudaGetSymbolAddress((void**)&stE,  g_statsE);
    cudaGetSymbolAddress((void**)&stH,  g_statsH);
    cudaGetSymbolAddress((void**)&ehi,  g_ehi);
    cudaGetSymbolAddress((void**)&elo,  g_elo);
    cudaGetSymbolAddress((void**)&hhi,  g_hhi);
    cudaGetSymbolAddress((void**)&hlo,  g_hlo);
    cudaGetSymbolAddress((void**)&wthi, g_wthi);
    cudaGetSymbolAddress((void**)&wtlo, g_wtlo);

    cudaFuncSetAttribute((const void*)gemm_mma,
                         cudaFuncAttributeMaxDynamicSharedMemorySize, GEMM_SMEM);

    const size_t WM = (size_t)FF * FF;      // 65536 per matrix

    // weight transpose + bf16 split (6 types x LL layers)
    for (int t = 0; t < 6; t++)
        prep_w<<<LL * 256, 256>>>(Wsrc[t], wthi + (size_t)t * LL * WM,
                                  wtlo + (size_t)t * LL * WM);

    // layer-0 input splits
    split8<<<4096, 256>>>(h0, hhi, hlo, (size_t)NN * FF / 8);
    split8<<<8192, 256>>>(e0, ehi, elo, (size_t)EE * FF / 8);

    dim3 gNode(2, (NN + 127) / 128);   // (2, 391)
    dim3 gEdge(2, EE / 128);           // (2, 6250)

    for (int l = 0; l < LL; l++) {
        const float* hcur = l ? outh : h0;
        const float* ecur = l ? oute : e0;
        size_t wo = (size_t)l * WM;

        // tensor-core GEMMs (bf16 hi/lo split, mma.sync)
        gemm_mma<<<gEdge, 256, GEMM_SMEM>>>(ehi, elo,
            wthi + 0 * LL * WM + wo, wtlo + 0 * LL * WM + wo, etmp, EE);
        gemm_mma<<<gNode, 256, GEMM_SMEM>>>(hhi, hlo,
            wthi + 1 * LL * WM + wo, wtlo + 1 * LL * WM + wo, hWs, NN);
        gemm_mma<<<gNode, 256, GEMM_SMEM>>>(hhi, hlo,
            wthi + 2 * LL * WM + wo, wtlo + 2 * LL * WM + wo, hWd, NN);
        gemm_mma<<<gNode, 256, GEMM_SMEM>>>(hhi, hlo,
            wthi + 3 * LL * WM + wo, wtlo + 3 * LL * WM + wo, htmp, NN);
        gemm_mma<<<gNode, 256, GEMM_SMEM>>>(hhi, hlo,
            wthi + 4 * LL * WM + wo, wtlo + 4 * LL * WM + wo, hWf, NN);
        gemm_mma<<<gNode, 256, GEMM_SMEM>>>(hhi, hlo,
            wthi + 5 * LL * WM + wo, wtlo + 5 * LL * WM + wo, hWb, NN);

        // per-layer scratch init
        fill_f<<<4096, 256>>>(aggf, (size_t)NN * FF, 0.f);
        fill_f<<<4096, 256>>>(aggb, (size_t)NN * FF, 0.f);
        fill_f<<<64, 256>>>(denf, NN, 0.f);
        fill_f<<<64, 256>>>(denb, NN, 0.f);
        fill_u<<<64, 256>>>((unsigned*)mf, NN, 0xFFFFFFFFu);
        fill_u<<<64, 256>>>((unsigned*)mb, NN, 0xFFFFFFFFu);
        fill_f<<<1, 512>>>(stE, 2 * FF, 0.f);
        fill_f<<<1, 512>>>(stH, 2 * FF, 0.f);

        int wsplit = (l < LL - 1) ? 1 : 0;

        edgeA_kernel<<<1024, 256>>>(etmp, hWs, hWd, src, dst,
                                    att_f + (size_t)l * FF, att_b + (size_t)l * FF,
                                    logf, logb, mf, mb, stE);
        bnfin_kernel<<<1, FF>>>(stE, 1.f / EE);
        edgeB_kernel<<<2048, 256>>>(etmp, ecur, oute, logf, logb, mf, mb,
                                    src, dst, hWf, hWb, denf, denb, aggf, aggb,
                                    stE, g_e + (size_t)l * FF, b_e + (size_t)l * FF,
                                    ehi, elo, wsplit);
        nodeA_kernel<<<512, 256>>>(htmp, aggf, aggb, denf, denb, stH);
        bnfin_kernel<<<1, FF>>>(stH, 1.f / NN);
        nodeB_kernel<<<(NN * FF / 8 + 255) / 256, 256>>>(
            htmp, hcur, outh, stH, g_h + (size_t)l * FF, b_h + (size_t)l * FF,
            hhi, hlo, wsplit);
    }
}